// round 11
// baseline (speedup 1.0000x reference)
#include <cuda_runtime.h>
#include <cuda_bf16.h>
#include <math.h>
#include <float.h>
#include <stdint.h>

// Problem constants
#define NS 2048        // n
#define BB 4096        // 2n
#define DD 512         // feature dim
#define CC 128         // num classes
#define KC 12          // candidates per (row,tile) and final candidate count
#define NT_COL 32      // 4096/128 column tiles
#define NTILES 528     // upper-triangular 32x32 tile count

// Scratch (allocation-free rule: __device__ globals)
__device__ float g_sq[BB];                                          // exact fp32 row squared norms
__device__ float g_part[BB];                                        // per-row partial sums
__device__ int g_ctr;                                               // last-block counter
__device__ __align__(16) __nv_bfloat16 g_fb[(size_t)BB * DD];       // 4 MB bf16 feats
__device__ __align__(16) uint32_t g_cand[(size_t)BB * NT_COL * KC]; // 6.3 MB packed keys

// ---------------------------------------------------------------------------
// helpers
// ---------------------------------------------------------------------------
__device__ __forceinline__ uint32_t smem_u32(const void* p) {
    uint32_t a;
    asm("{ .reg .u64 t; cvta.to.shared.u64 t, %1; cvt.u32.u64 %0, t; }" : "=r"(a) : "l"(p));
    return a;
}
__device__ __forceinline__ void cp16(uint32_t dst, const void* src) {
    asm volatile("cp.async.cg.shared.global [%0], [%1], 16;" :: "r"(dst), "l"(src) : "memory");
}
#define CP_COMMIT() asm volatile("cp.async.commit_group;" ::: "memory")
#define CP_WAIT(N)  asm volatile("cp.async.wait_group %0;" :: "n"(N) : "memory")

#define LDSM_X4(d, addr) \
    asm volatile("ldmatrix.sync.aligned.m8n8.x4.shared.b16 {%0,%1,%2,%3}, [%4];" \
                 : "=r"((d)[0]), "=r"((d)[1]), "=r"((d)[2]), "=r"((d)[3]) : "r"(addr))

#define MMA16816(c, a, b0, b1) \
    asm volatile("mma.sync.aligned.m16n8k16.row.col.f32.bf16.bf16.f32 " \
                 "{%0,%1,%2,%3}, {%4,%5,%6,%7}, {%8,%9}, {%0,%1,%2,%3};" \
                 : "+f"((c)[0]), "+f"((c)[1]), "+f"((c)[2]), "+f"((c)[3]) \
                 : "r"((a)[0]), "r"((a)[1]), "r"((a)[2]), "r"((a)[3]), "r"(b0), "r"(b1))

// monotone float->uint order map, low 7 bits replaced by tile-local index
__device__ __forceinline__ uint32_t pack_key(float s, int idx) {
    uint32_t u = __float_as_uint(s);
    u ^= ((uint32_t)((int32_t)u >> 31)) | 0x80000000u;
    return (u & 0xFFFFFF80u) | (uint32_t)idx;
}

// ---------------------------------------------------------------------------
// Kernel 0: fused fp32->bf16 conversion + exact fp32 row norms. Warp per row.
// Also resets the last-block counter (graph-replay safe).
// ---------------------------------------------------------------------------
__global__ void convsq_kernel(const float* __restrict__ zi, const float* __restrict__ zj) {
    if (blockIdx.x == 0 && threadIdx.x == 0) g_ctr = 0;
    int w = (blockIdx.x * blockDim.x + threadIdx.x) >> 5;
    int lane = threadIdx.x & 31;
    if (w >= BB) return;
    const float* p = (w < NS) ? zi + (size_t)w * DD : zj + (size_t)(w - NS) * DD;
    const float4* p4 = (const float4*)p;
    __nv_bfloat162* dst = (__nv_bfloat162*)(g_fb + (size_t)w * DD);
    float s = 0.f;
    #pragma unroll
    for (int k = lane; k < DD / 4; k += 32) {
        float4 v = p4[k];
        s += v.x * v.x + v.y * v.y + v.z * v.z + v.w * v.w;
        dst[2 * k]     = __floats2bfloat162_rn(v.x, v.y);
        dst[2 * k + 1] = __floats2bfloat162_rn(v.z, v.w);
    }
    #pragma unroll
    for (int o = 16; o; o >>= 1) s += __shfl_xor_sync(0xffffffffu, s, o);
    if (lane == 0) g_sq[w] = s;
}

// ---------------------------------------------------------------------------
// Kernel 2: SYMMETRIC bf16 mma.sync GEMM — 528 upper-tri 128x128 tiles,
// 3-stage cp.async pipeline (ONE __syncthreads per k-tile). Epilogue stages
// raw dots, then REDUX-based per-(row,tile) top-12 in row + col passes.
// ---------------------------------------------------------------------------
#define KT    16            // 512 / 32 k-tiles
#define SROW  40            // smem row stride in bf16 elems (80 B)
#define SLOT  20480         // bytes per pipeline slot (A 10240 + B 10240)
#define STG_STRIDE 132      // stage row stride in words
#define DYN_SMEM (128 * STG_STRIDE * 4)   // 67584 B (covers 3 x 20480 slots)

__global__ void __launch_bounds__(256, 2) gemm_select_kernel() {
    extern __shared__ __align__(16) char dsm[];
    __shared__ float s_sqm[128], s_sqn[128];

    float* stg = (float*)dsm;                            // [128][132] raw dots

    const int tid = threadIdx.x;
    const int lane = tid & 31;
    const int wid = tid >> 5;
    const int wy = wid >> 2;
    const int wx = wid & 3;

    // upper-tri tile map: blockIdx.x -> (bi, bj), bj >= bi
    int t = blockIdx.x;
    int bi = 0;
    while (t >= NT_COL - bi) { t -= NT_COL - bi; ++bi; }
    const int bj = bi + t;
    const int m0 = bi << 7;
    const int n0 = bj << 7;
    const bool diag = (bi == bj);

    if (tid < 128) { s_sqm[tid] = g_sq[m0 + tid]; s_sqn[tid] = g_sq[n0 + tid]; }

    const int lr = tid >> 1;
    const int lu = (tid & 1) * 16;
    const uint32_t sbase = smem_u32(dsm);
    const uint32_t sdoff = (uint32_t)(lr * SROW + lu) * 2;
    const __nv_bfloat16* gA = g_fb + (size_t)(m0 + lr) * DD + lu;
    const __nv_bfloat16* gB = g_fb + (size_t)(n0 + lr) * DD + lu;

    const int rowA = wy * 64 + (lane & 7) + ((lane >> 3) & 1) * 8;
    const int colA = (lane >> 4) * 8;
    const int rowB = wx * 32 + (lane & 7) + (lane >> 4) * 8;
    const int colB = ((lane >> 3) & 1) * 8;

    float acc[4][4][4];
    #pragma unroll
    for (int i = 0; i < 4; i++)
        #pragma unroll
        for (int j = 0; j < 4; j++)
            #pragma unroll
            for (int q = 0; q < 4; q++) acc[i][j][q] = 0.f;

    auto issue = [&](int kt, int slot) {
        const uint32_t b = sbase + (uint32_t)slot * SLOT;
        const __nv_bfloat16* pa = gA + kt * 32;
        const __nv_bfloat16* pb = gB + kt * 32;
        cp16(b + sdoff, pa);              cp16(b + sdoff + 16, pa + 8);
        cp16(b + 10240 + sdoff, pb);      cp16(b + 10240 + sdoff + 16, pb + 8);
        CP_COMMIT();
    };

    issue(0, 0);
    issue(1, 1);

    int cs = 0;
    for (int kt = 0; kt < KT; ++kt) {
        if (kt < KT - 1) { CP_WAIT(1); } else { CP_WAIT(0); }
        __syncthreads();                 // kt's data landed; slot (kt-1)%3 free
        if (kt + 2 < KT) {
            int is = cs + 2; if (is >= 3) is -= 3;
            issue(kt + 2, is);
        }
        const uint32_t ab = sbase + (uint32_t)cs * SLOT;
        const uint32_t bb = ab + 10240u;
        #pragma unroll
        for (int ks = 0; ks < 2; ++ks) {
            uint32_t a[4][4], b[2][4];
            #pragma unroll
            for (int mi = 0; mi < 4; mi++)
                LDSM_X4(a[mi], ab + (uint32_t)((rowA + mi * 16) * SROW + ks * 16 + colA) * 2);
            #pragma unroll
            for (int ng = 0; ng < 2; ng++)
                LDSM_X4(b[ng], bb + (uint32_t)((rowB + ng * 16) * SROW + ks * 16 + colB) * 2);
            #pragma unroll
            for (int mi = 0; mi < 4; mi++)
                #pragma unroll
                for (int nb = 0; nb < 4; nb++)
                    MMA16816(acc[mi][nb], a[mi], b[nb >> 1][(nb & 1) * 2], b[nb >> 1][(nb & 1) * 2 + 1]);
        }
        if (++cs == 3) cs = 0;
    }
    __syncthreads();   // all MMAs done before the stage region is overwritten

    // stage raw dot values; acc registers die here
    {
        const int er = (lane >> 2);
        const int ec = wx * 32 + (lane & 3) * 2;
        #pragma unroll
        for (int mi = 0; mi < 4; mi++) {
            const int ra = wy * 64 + mi * 16 + er;
            const int rb = ra + 8;
            #pragma unroll
            for (int nb = 0; nb < 4; nb++) {
                const int cc = ec + nb * 8;
                stg[ra * STG_STRIDE + cc]     = acc[mi][nb][0];
                stg[ra * STG_STRIDE + cc + 1] = acc[mi][nb][1];
                stg[rb * STG_STRIDE + cc]     = acc[mi][nb][2];
                stg[rb * STG_STRIDE + cc + 1] = acc[mi][nb][3];
            }
        }
    }
    __syncthreads();

    const int g8 = lane >> 2;
    const int l4 = lane & 3;
    const uint32_t qmask = 0xFu << (g8 * 4);

    // ---- ROW PASS: rank cols (block bj) for each m-row ----
    #pragma unroll 1
    for (int rp = 0; rp < 2; ++rp) {
        const int relrow = rp * 64 + wid * 8 + g8;     // 0..127
        uint32_t keys[KC];
        #pragma unroll
        for (int q = 0; q < KC; q++) keys[q] = 0xFFFFFFFFu;

        const float* srow = stg + relrow * STG_STRIDE;
        #pragma unroll
        for (int q = 0; q < 8; ++q) {
            float4 d4 = *(const float4*)(srow + q * 16 + l4 * 4);
            const int cb = q * 16 + l4 * 4;
            float dv[4] = {d4.x, d4.y, d4.z, d4.w};
            #pragma unroll
            for (int k = 0; k < 4; k++) {
                const int c = cb + k;
                uint32_t u = pack_key(fmaf(-2.f, dv[k], s_sqn[c]), c);
                if (diag && c == relrow) u = 0xFFFFFFFFu;
                if (u < keys[KC - 1]) {
                    keys[KC - 1] = u;
                    #pragma unroll
                    for (int s = KC - 1; s >= 1; s--) {
                        if (keys[s] < keys[s - 1]) {
                            uint32_t tt = keys[s]; keys[s] = keys[s - 1]; keys[s - 1] = tt;
                        }
                    }
                }
            }
        }

        uint32_t* crow = g_cand + ((size_t)(m0 + relrow) * NT_COL + bj) * KC;
        #pragma unroll
        for (int r = 0; r < KC; ++r) {
            uint32_t mv = __reduce_min_sync(qmask, keys[0]);
            if (keys[0] == mv) {            // unique owner pops its head
                #pragma unroll
                for (int s = 0; s < KC - 1; s++) keys[s] = keys[s + 1];
                keys[KC - 1] = 0xFFFFFFFFu;
            }
            if (l4 == 0) crow[r] = mv;
        }
    }

    // ---- COL PASS (off-diagonal only): rank rows (block bi) for each n-col ----
    if (!diag) {
        #pragma unroll 1
        for (int rp = 0; rp < 2; ++rp) {
            const int relcol = rp * 64 + wid * 8 + g8;   // 0..127
            uint32_t keys[KC];
            #pragma unroll
            for (int q = 0; q < KC; q++) keys[q] = 0xFFFFFFFFu;

            #pragma unroll 2
            for (int b = 0; b < 8; ++b) {
                float dd[4];
                #pragma unroll
                for (int u = 0; u < 4; ++u)
                    dd[u] = stg[(l4 + 16 * b + 4 * u) * STG_STRIDE + relcol];
                #pragma unroll
                for (int u = 0; u < 4; ++u) {
                    const int r = l4 + 16 * b + 4 * u;
                    uint32_t uk = pack_key(fmaf(-2.f, dd[u], s_sqm[r]), r);
                    if (uk < keys[KC - 1]) {
                        keys[KC - 1] = uk;
                        #pragma unroll
                        for (int s = KC - 1; s >= 1; s--) {
                            if (keys[s] < keys[s - 1]) {
                                uint32_t tt = keys[s]; keys[s] = keys[s - 1]; keys[s - 1] = tt;
                            }
                        }
                    }
                }
            }

            uint32_t* crow = g_cand + ((size_t)(n0 + relcol) * NT_COL + bi) * KC;
            #pragma unroll
            for (int r = 0; r < KC; ++r) {
                uint32_t mv = __reduce_min_sync(qmask, keys[0]);
                if (keys[0] == mv) {
                    #pragma unroll
                    for (int s = 0; s < KC - 1; s++) keys[s] = keys[s + 1];
                    keys[KC - 1] = 0xFFFFFFFFu;
                }
                if (l4 == 0) crow[r] = mv;
            }
        }
    }
}

// ---------------------------------------------------------------------------
// Kernel 3: merge 32x12 packed per-tile candidates -> approx top-12 -> exact
// fp32 rescore (MLP-batched) -> exact top-10 -> weights, masked prob-dots.
// Warp per row. Last-arriving block does the deterministic final reduction.
// ---------------------------------------------------------------------------
__global__ void merge_loss_kernel(const float* __restrict__ zi,
                                  const float* __restrict__ zj,
                                  const float* __restrict__ zip,
                                  const float* __restrict__ zjp,
                                  const int* __restrict__ label,
                                  float* __restrict__ out) {
    int w = (blockIdx.x * blockDim.x + threadIdx.x) >> 5;
    int lane = threadIdx.x & 31;
    const int i = w;
    const uint32_t* crow = g_cand + (size_t)i * (NT_COL * KC);

    // per-lane sorted top-12 over its 12 assigned candidates
    uint32_t v[KC]; int c[KC];
    #pragma unroll
    for (int q = 0; q < KC; q++) { v[q] = 0xFFFFFFFFu; c[q] = 0x7fffffff; }
    #pragma unroll
    for (int t = 0; t < KC; ++t) {
        const int e = t * 32 + lane;          // 0..383
        const uint32_t k = crow[e];
        const int tile = e / KC;
        const int gcol = tile * 128 + (int)(k & 127u);
        if (k < v[KC - 1]) {
            v[KC - 1] = k; c[KC - 1] = gcol;
            #pragma unroll
            for (int q = KC - 1; q >= 1; q--) {
                if (v[q] < v[q - 1]) {
                    uint32_t tv = v[q]; v[q] = v[q - 1]; v[q - 1] = tv;
                    int tc = c[q]; c[q] = c[q - 1]; c[q - 1] = tc;
                }
            }
        }
    }

    // full-warp merge: 12 rounds of REDUX-min extract (tie -> lowest lane;
    // order immaterial: the extracted SET is fixed and rescore re-sorts)
    int rc[KC];
    #pragma unroll
    for (int r = 0; r < KC; r++) {
        uint32_t mv = __reduce_min_sync(0xffffffffu, v[0]);
        unsigned own = __ballot_sync(0xffffffffu, v[0] == mv);
        int leader = __ffs(own) - 1;
        rc[r] = __shfl_sync(0xffffffffu, c[0], leader);
        if (lane == leader) {
            #pragma unroll
            for (int q = 0; q < KC - 1; q++) { v[q] = v[q + 1]; c[q] = c[q + 1]; }
            v[KC - 1] = 0xFFFFFFFFu; c[KC - 1] = 0x7fffffff;
        }
    }

    // exact fp32 rescore of the 12 candidates — MLP-batched loads
    const float* fip = (i < NS) ? zi + (size_t)i * DD : zj + (size_t)(i - NS) * DD;
    float4 fi[4];
    #pragma unroll
    for (int q = 0; q < 4; q++) fi[q] = ((const float4*)fip)[lane + 32 * q];
    const float sqi = g_sq[i];

    const float* fps[KC];
    #pragma unroll
    for (int r = 0; r < KC; r++)
        fps[r] = (rc[r] < NS) ? zi + (size_t)rc[r] * DD : zj + (size_t)(rc[r] - NS) * DD;

    float sacc[KC];
    #pragma unroll
    for (int r = 0; r < KC; r++) sacc[r] = 0.f;
    #pragma unroll
    for (int q = 0; q < 4; q++) {
        const float4 f = fi[q];
        float4 fj[KC];
        #pragma unroll
        for (int r = 0; r < KC; r++) fj[r] = ((const float4*)fps[r])[lane + 32 * q];
        #pragma unroll
        for (int r = 0; r < KC; r++)
            sacc[r] += f.x * fj[r].x + f.y * fj[r].y + f.z * fj[r].z + f.w * fj[r].w;
    }

    float rd[KC];
    #pragma unroll
    for (int r = 0; r < KC; r++) {
        float s = sacc[r];
        #pragma unroll
        for (int o = 16; o; o >>= 1) s += __shfl_xor_sync(0xffffffffu, s, o);
        rd[r] = sqi + g_sq[rc[r]] - 2.f * s;       // exact d2 (all lanes agree)
    }

    // per-lane redundant sort of 12 (ascending d2, index tiebreak)
    #pragma unroll
    for (int a = 1; a < KC; a++) {
        float dv = rd[a]; int ci = rc[a];
        int b = a;
        while (b > 0 && (rd[b - 1] > dv || (rd[b - 1] == dv && rc[b - 1] > ci))) {
            rd[b] = rd[b - 1]; rc[b] = rc[b - 1]; --b;
        }
        rd[b] = dv; rc[b] = ci;
    }

    // weights + masked prob-dots over exact top-10
    float radius = sqrtf(fmaxf(rd[0], 0.f));
    const float* prow = (i < NS) ? zip + (size_t)i * CC : zjp + (size_t)(i - NS) * CC;
    float4 myp = ((const float4*)prow)[lane];
    const int im = i & (NS - 1);
    const int li = label[im];
    float rowsum = 0.f;
    #pragma unroll
    for (int r = 0; r < 10; r++) {
        int j = rc[r];
        int jm = j & (NS - 1);
        if (li == label[jm] && li != -1 && im != jm) {
            const float* pr = (j < NS) ? zip + (size_t)j * CC : zjp + (size_t)(j - NS) * CC;
            float4 q4 = ((const float4*)pr)[lane];
            float part = myp.x * q4.x + myp.y * q4.y + myp.z * q4.z + myp.w * q4.w;
            #pragma unroll
            for (int o = 16; o; o >>= 1) part += __shfl_xor_sync(0xffffffffu, part, o);
            float pd = sqrtf(fmaxf(rd[r], 0.f));
            float ww = 1.f - fminf(fmaxf((pd - radius) / radius, 0.f), 1.f);
            rowsum += ww * part;
        }
    }
    if (lane == 0) g_part[i] = rowsum;

    // ---- last-block deterministic reduction ----
    __shared__ int s_last;
    __shared__ float s_red[256];
    __threadfence();
    __syncthreads();
    if (threadIdx.x == 0) s_last = (atomicAdd(&g_ctr, 1) == gridDim.x - 1) ? 1 : 0;
    __syncthreads();
    if (s_last) {
        int tdx = threadIdx.x;
        float a = 0.f;
        #pragma unroll
        for (int q = 0; q < 16; q++) a += g_part[tdx + 256 * q];
        s_red[tdx] = a;
        __syncthreads();
        for (int o = 128; o; o >>= 1) {
            if (tdx < o) s_red[tdx] += s_red[tdx + o];
            __syncthreads();
        }
        if (tdx == 0) out[0] = s_red[0] * (1.0f / ((float)BB * (float)BB));
    }
}

// ---------------------------------------------------------------------------
extern "C" void kernel_launch(void* const* d_in, const int* in_sizes, int n_in,
                              void* d_out, int out_size) {
    const float* z_i = (const float*)d_in[0];
    const float* z_j = (const float*)d_in[1];
    const float* z_i_prob = (const float*)d_in[2];
    const float* z_j_prob = (const float*)d_in[3];
    const int* pseudo_label = (const int*)d_in[4];
    float* out = (float*)d_out;

    cudaFuncSetAttribute(gemm_select_kernel,
                         cudaFuncAttributeMaxDynamicSharedMemorySize, DYN_SMEM);

    convsq_kernel<<<BB / 8, 256>>>(z_i, z_j);
    gemm_select_kernel<<<NTILES, 256, DYN_SMEM>>>();
    merge_loss_kernel<<<BB / 8, 256>>>(z_i, z_j, z_i_prob, z_j_prob, pseudo_label, out);
}

// round 12
// speedup vs baseline: 1.0020x; 1.0020x over previous
#include <cuda_runtime.h>
#include <cuda_bf16.h>
#include <math.h>
#include <float.h>
#include <stdint.h>

// Problem constants
#define NS 2048        // n
#define BB 4096        // 2n
#define DD 512         // feature dim
#define CC 128         // num classes
#define KC 12          // candidates per (row,tile) and final candidate count
#define NT_COL 32      // 4096/128 column tiles
#define NTILES 528     // upper-triangular 32x32 tile count

// Scratch (allocation-free rule: __device__ globals)
__device__ float g_sq[BB];                                          // exact fp32 row squared norms
__device__ float g_part[BB];                                        // per-row partial sums
__device__ int g_ctr;                                               // last-block counter
__device__ __align__(16) __nv_bfloat16 g_fb[(size_t)BB * DD];       // 4 MB bf16 feats
__device__ __align__(16) uint32_t g_cand[(size_t)BB * NT_COL * KC]; // 6.3 MB packed keys

// ---------------------------------------------------------------------------
// helpers
// ---------------------------------------------------------------------------
__device__ __forceinline__ uint32_t smem_u32(const void* p) {
    uint32_t a;
    asm("{ .reg .u64 t; cvta.to.shared.u64 t, %1; cvt.u32.u64 %0, t; }" : "=r"(a) : "l"(p));
    return a;
}
__device__ __forceinline__ void cp16(uint32_t dst, const void* src) {
    asm volatile("cp.async.cg.shared.global [%0], [%1], 16;" :: "r"(dst), "l"(src) : "memory");
}
#define CP_COMMIT() asm volatile("cp.async.commit_group;" ::: "memory")
#define CP_WAIT(N)  asm volatile("cp.async.wait_group %0;" :: "n"(N) : "memory")

#define LDSM_X4(d, addr) \
    asm volatile("ldmatrix.sync.aligned.m8n8.x4.shared.b16 {%0,%1,%2,%3}, [%4];" \
                 : "=r"((d)[0]), "=r"((d)[1]), "=r"((d)[2]), "=r"((d)[3]) : "r"(addr))

#define MMA16816(c, a, b0, b1) \
    asm volatile("mma.sync.aligned.m16n8k16.row.col.f32.bf16.bf16.f32 " \
                 "{%0,%1,%2,%3}, {%4,%5,%6,%7}, {%8,%9}, {%0,%1,%2,%3};" \
                 : "+f"((c)[0]), "+f"((c)[1]), "+f"((c)[2]), "+f"((c)[3]) \
                 : "r"((a)[0]), "r"((a)[1]), "r"((a)[2]), "r"((a)[3]), "r"(b0), "r"(b1))

// monotone float->uint order map, low 7 bits replaced by tile-local index
__device__ __forceinline__ uint32_t pack_key(float s, int idx) {
    uint32_t u = __float_as_uint(s);
    u ^= ((uint32_t)((int32_t)u >> 31)) | 0x80000000u;
    return (u & 0xFFFFFF80u) | (uint32_t)idx;
}

// ---------------------------------------------------------------------------
// Kernel 0: fused fp32->bf16 conversion + exact fp32 row norms. Warp per row.
// Also resets the last-block counter (graph-replay safe).
// ---------------------------------------------------------------------------
__global__ void convsq_kernel(const float* __restrict__ zi, const float* __restrict__ zj) {
    if (blockIdx.x == 0 && threadIdx.x == 0) g_ctr = 0;
    int w = (blockIdx.x * blockDim.x + threadIdx.x) >> 5;
    int lane = threadIdx.x & 31;
    if (w >= BB) return;
    const float* p = (w < NS) ? zi + (size_t)w * DD : zj + (size_t)(w - NS) * DD;
    const float4* p4 = (const float4*)p;
    __nv_bfloat162* dst = (__nv_bfloat162*)(g_fb + (size_t)w * DD);
    float s = 0.f;
    #pragma unroll
    for (int k = lane; k < DD / 4; k += 32) {
        float4 v = p4[k];
        s += v.x * v.x + v.y * v.y + v.z * v.z + v.w * v.w;
        dst[2 * k]     = __floats2bfloat162_rn(v.x, v.y);
        dst[2 * k + 1] = __floats2bfloat162_rn(v.z, v.w);
    }
    #pragma unroll
    for (int o = 16; o; o >>= 1) s += __shfl_xor_sync(0xffffffffu, s, o);
    if (lane == 0) g_sq[w] = s;
}

// ---------------------------------------------------------------------------
// Kernel 2: SYMMETRIC bf16 mma.sync GEMM — 528 upper-tri 128x128 tiles,
// R9 2-stage double-buffered mainloop. Epilogue stages raw dots, then
// REDUX-min per-(row,tile) top-12 in row + col passes (the single change).
// ---------------------------------------------------------------------------
#define KT    16            // 512 / 32 k-tiles
#define SROW  40            // smem row stride in bf16 elems (80 B)
#define SBUF  (128 * SROW)  // elems per tile buffer (5120)
#define STG_STRIDE 132      // stage row stride in words
#define DYN_SMEM (128 * STG_STRIDE * 4)   // 67584 B (covers the 40960 B A/B bufs)

__global__ void __launch_bounds__(256, 2) gemm_select_kernel() {
    extern __shared__ __align__(16) char dsm[];
    __shared__ float s_sqm[128], s_sqn[128];

    __nv_bfloat16* As = (__nv_bfloat16*)dsm;             // [2][SBUF]
    __nv_bfloat16* Bs = (__nv_bfloat16*)(dsm + 20480);   // [2][SBUF]
    float* stg = (float*)dsm;                            // [128][132] raw dots

    const int tid = threadIdx.x;
    const int lane = tid & 31;
    const int wid = tid >> 5;
    const int wy = wid >> 2;
    const int wx = wid & 3;

    // upper-tri tile map: blockIdx.x -> (bi, bj), bj >= bi
    int t = blockIdx.x;
    int bi = 0;
    while (t >= NT_COL - bi) { t -= NT_COL - bi; ++bi; }
    const int bj = bi + t;
    const int m0 = bi << 7;
    const int n0 = bj << 7;
    const bool diag = (bi == bj);

    if (tid < 128) { s_sqm[tid] = g_sq[m0 + tid]; s_sqn[tid] = g_sq[n0 + tid]; }

    const int lr = tid >> 1;
    const int lu = (tid & 1) * 16;
    const uint32_t sA = smem_u32(As);
    const uint32_t sB = smem_u32(Bs);
    const uint32_t sdoff = (uint32_t)(lr * SROW + lu) * 2;
    const __nv_bfloat16* gA = g_fb + (size_t)(m0 + lr) * DD + lu;
    const __nv_bfloat16* gB = g_fb + (size_t)(n0 + lr) * DD + lu;

    const int rowA = wy * 64 + (lane & 7) + ((lane >> 3) & 1) * 8;
    const int colA = (lane >> 4) * 8;
    const int rowB = wx * 32 + (lane & 7) + (lane >> 4) * 8;
    const int colB = ((lane >> 3) & 1) * 8;

    float acc[4][4][4];
    #pragma unroll
    for (int i = 0; i < 4; i++)
        #pragma unroll
        for (int j = 0; j < 4; j++)
            #pragma unroll
            for (int q = 0; q < 4; q++) acc[i][j][q] = 0.f;

    {
        cp16(sA + sdoff, gA); cp16(sA + sdoff + 16, gA + 8);
        cp16(sB + sdoff, gB); cp16(sB + sdoff + 16, gB + 8);
        CP_COMMIT();
    }

    for (int kt = 0; kt < KT; ++kt) {
        const int buf = kt & 1;
        if (kt + 1 < KT) {
            const uint32_t boff = (uint32_t)(buf ^ 1) * (SBUF * 2);
            const __nv_bfloat16* pa = gA + (kt + 1) * 32;
            const __nv_bfloat16* pb = gB + (kt + 1) * 32;
            cp16(sA + boff + sdoff, pa); cp16(sA + boff + sdoff + 16, pa + 8);
            cp16(sB + boff + sdoff, pb); cp16(sB + boff + sdoff + 16, pb + 8);
            CP_COMMIT();
            CP_WAIT(1);
        } else {
            CP_WAIT(0);
        }
        __syncthreads();

        const uint32_t ab = sA + (uint32_t)buf * (SBUF * 2);
        const uint32_t bb = sB + (uint32_t)buf * (SBUF * 2);
        #pragma unroll
        for (int ks = 0; ks < 2; ++ks) {
            uint32_t a[4][4], b[2][4];
            #pragma unroll
            for (int mi = 0; mi < 4; mi++)
                LDSM_X4(a[mi], ab + (uint32_t)((rowA + mi * 16) * SROW + ks * 16 + colA) * 2);
            #pragma unroll
            for (int ng = 0; ng < 2; ng++)
                LDSM_X4(b[ng], bb + (uint32_t)((rowB + ng * 16) * SROW + ks * 16 + colB) * 2);
            #pragma unroll
            for (int mi = 0; mi < 4; mi++)
                #pragma unroll
                for (int nb = 0; nb < 4; nb++)
                    MMA16816(acc[mi][nb], a[mi], b[nb >> 1][(nb & 1) * 2], b[nb >> 1][(nb & 1) * 2 + 1]);
        }
        __syncthreads();
    }
    // A/B smem dead; stage raw dot values so acc registers die here.

    {
        const int er = (lane >> 2);
        const int ec = wx * 32 + (lane & 3) * 2;
        #pragma unroll
        for (int mi = 0; mi < 4; mi++) {
            const int ra = wy * 64 + mi * 16 + er;
            const int rb = ra + 8;
            #pragma unroll
            for (int nb = 0; nb < 4; nb++) {
                const int cc = ec + nb * 8;
                stg[ra * STG_STRIDE + cc]     = acc[mi][nb][0];
                stg[ra * STG_STRIDE + cc + 1] = acc[mi][nb][1];
                stg[rb * STG_STRIDE + cc]     = acc[mi][nb][2];
                stg[rb * STG_STRIDE + cc + 1] = acc[mi][nb][3];
            }
        }
    }
    __syncthreads();

    const int g8 = lane >> 2;
    const int l4 = lane & 3;
    const uint32_t qmask = 0xFu << (g8 * 4);

    // ---- ROW PASS: rank cols (block bj) for each m-row ----
    #pragma unroll 1
    for (int rp = 0; rp < 2; ++rp) {
        const int relrow = rp * 64 + wid * 8 + g8;     // 0..127
        uint32_t keys[KC];
        #pragma unroll
        for (int q = 0; q < KC; q++) keys[q] = 0xFFFFFFFFu;

        const float* srow = stg + relrow * STG_STRIDE;
        #pragma unroll
        for (int q = 0; q < 8; ++q) {
            float4 d4 = *(const float4*)(srow + q * 16 + l4 * 4);
            const int cb = q * 16 + l4 * 4;
            float dv[4] = {d4.x, d4.y, d4.z, d4.w};
            #pragma unroll
            for (int k = 0; k < 4; k++) {
                const int c = cb + k;
                uint32_t u = pack_key(fmaf(-2.f, dv[k], s_sqn[c]), c);
                if (diag && c == relrow) u = 0xFFFFFFFFu;
                if (u < keys[KC - 1]) {
                    keys[KC - 1] = u;
                    #pragma unroll
                    for (int s = KC - 1; s >= 1; s--) {
                        if (keys[s] < keys[s - 1]) {
                            uint32_t tt = keys[s]; keys[s] = keys[s - 1]; keys[s - 1] = tt;
                        }
                    }
                }
            }
        }

        // quad merge: REDUX-min extraction (keys unique in tile -> unique owner)
        uint32_t* crow = g_cand + ((size_t)(m0 + relrow) * NT_COL + bj) * KC;
        #pragma unroll
        for (int r = 0; r < KC; ++r) {
            uint32_t mv = __reduce_min_sync(qmask, keys[0]);
            if (keys[0] == mv) {
                #pragma unroll
                for (int s = 0; s < KC - 1; s++) keys[s] = keys[s + 1];
                keys[KC - 1] = 0xFFFFFFFFu;
            }
            if (l4 == 0) crow[r] = mv;
        }
    }

    // ---- COL PASS (off-diagonal only): rank rows (block bi) for each n-col ----
    if (!diag) {
        #pragma unroll 1
        for (int rp = 0; rp < 2; ++rp) {
            const int relcol = rp * 64 + wid * 8 + g8;   // 0..127
            uint32_t keys[KC];
            #pragma unroll
            for (int q = 0; q < KC; q++) keys[q] = 0xFFFFFFFFu;

            #pragma unroll 2
            for (int b = 0; b < 8; ++b) {
                float dd[4];
                #pragma unroll
                for (int u = 0; u < 4; ++u)
                    dd[u] = stg[(l4 + 16 * b + 4 * u) * STG_STRIDE + relcol];
                #pragma unroll
                for (int u = 0; u < 4; ++u) {
                    const int r = l4 + 16 * b + 4 * u;
                    uint32_t uk = pack_key(fmaf(-2.f, dd[u], s_sqm[r]), r);
                    if (uk < keys[KC - 1]) {
                        keys[KC - 1] = uk;
                        #pragma unroll
                        for (int s = KC - 1; s >= 1; s--) {
                            if (keys[s] < keys[s - 1]) {
                                uint32_t tt = keys[s]; keys[s] = keys[s - 1]; keys[s - 1] = tt;
                            }
                        }
                    }
                }
            }

            uint32_t* crow = g_cand + ((size_t)(n0 + relcol) * NT_COL + bi) * KC;
            #pragma unroll
            for (int r = 0; r < KC; ++r) {
                uint32_t mv = __reduce_min_sync(qmask, keys[0]);
                if (keys[0] == mv) {
                    #pragma unroll
                    for (int s = 0; s < KC - 1; s++) keys[s] = keys[s + 1];
                    keys[KC - 1] = 0xFFFFFFFFu;
                }
                if (l4 == 0) crow[r] = mv;
            }
        }
    }
}

// ---------------------------------------------------------------------------
// Kernel 3: merge 32x12 packed per-tile candidates -> approx top-12 -> exact
// fp32 rescore (R9 sequential form, 56 regs) -> exact top-10 -> weights,
// masked prob-dots. Warp per row. Last block does the final reduction.
// ---------------------------------------------------------------------------
__global__ void merge_loss_kernel(const float* __restrict__ zi,
                                  const float* __restrict__ zj,
                                  const float* __restrict__ zip,
                                  const float* __restrict__ zjp,
                                  const int* __restrict__ label,
                                  float* __restrict__ out) {
    int w = (blockIdx.x * blockDim.x + threadIdx.x) >> 5;
    int lane = threadIdx.x & 31;
    const int i = w;
    const uint32_t* crow = g_cand + (size_t)i * (NT_COL * KC);

    // per-lane sorted top-12 over its 12 assigned candidates
    uint32_t v[KC]; int c[KC];
    #pragma unroll
    for (int q = 0; q < KC; q++) { v[q] = 0xFFFFFFFFu; c[q] = 0x7fffffff; }
    #pragma unroll
    for (int t = 0; t < KC; ++t) {
        const int e = t * 32 + lane;          // 0..383
        const uint32_t k = crow[e];
        const int tile = e / KC;
        const int gcol = tile * 128 + (int)(k & 127u);
        if (k < v[KC - 1]) {
            v[KC - 1] = k; c[KC - 1] = gcol;
            #pragma unroll
            for (int q = KC - 1; q >= 1; q--) {
                if (v[q] < v[q - 1]) {
                    uint32_t tv = v[q]; v[q] = v[q - 1]; v[q - 1] = tv;
                    int tc = c[q]; c[q] = c[q - 1]; c[q - 1] = tc;
                }
            }
        }
    }

    // full-warp merge: 12 rounds of argmin-extract (R9 form)
    int rc[KC];
    #pragma unroll
    for (int r = 0; r < KC; r++) {
        uint32_t mv = v[0]; int mc = c[0];
        #pragma unroll
        for (int o = 16; o; o >>= 1) {
            uint32_t ov = __shfl_down_sync(0xffffffffu, mv, o);
            int oc = __shfl_down_sync(0xffffffffu, mc, o);
            if (ov < mv || (ov == mv && oc < mc)) { mv = ov; mc = oc; }
        }
        mc = __shfl_sync(0xffffffffu, mc, 0);
        rc[r] = mc;
        if (c[0] == mc) {
            #pragma unroll
            for (int q = 0; q < KC - 1; q++) { v[q] = v[q + 1]; c[q] = c[q + 1]; }
            v[KC - 1] = 0xFFFFFFFFu; c[KC - 1] = 0x7fffffff;
        }
    }

    // exact fp32 rescore of the 12 candidates (sequential, low reg pressure)
    const float* fip = (i < NS) ? zi + (size_t)i * DD : zj + (size_t)(i - NS) * DD;
    float4 fi[4];
    #pragma unroll
    for (int q = 0; q < 4; q++) fi[q] = ((const float4*)fip)[lane + 32 * q];
    const float sqi = g_sq[i];

    float rd[KC];
    #pragma unroll
    for (int r = 0; r < KC; r++) {
        int j = rc[r];
        const float* fjp = (j < NS) ? zi + (size_t)j * DD : zj + (size_t)(j - NS) * DD;
        float s = 0.f;
        #pragma unroll
        for (int q = 0; q < 4; q++) {
            float4 fj = ((const float4*)fjp)[lane + 32 * q];
            s += fi[q].x * fj.x + fi[q].y * fj.y + fi[q].z * fj.z + fi[q].w * fj.w;
        }
        #pragma unroll
        for (int o = 16; o; o >>= 1) s += __shfl_xor_sync(0xffffffffu, s, o);
        rd[r] = sqi + g_sq[j] - 2.f * s;           // exact d2 (all lanes agree)
    }

    // per-lane redundant sort of 12 (ascending d2, index tiebreak)
    #pragma unroll
    for (int a = 1; a < KC; a++) {
        float dv = rd[a]; int ci = rc[a];
        int b = a;
        while (b > 0 && (rd[b - 1] > dv || (rd[b - 1] == dv && rc[b - 1] > ci))) {
            rd[b] = rd[b - 1]; rc[b] = rc[b - 1]; --b;
        }
        rd[b] = dv; rc[b] = ci;
    }

    // weights + masked prob-dots over exact top-10
    float radius = sqrtf(fmaxf(rd[0], 0.f));
    const float* prow = (i < NS) ? zip + (size_t)i * CC : zjp + (size_t)(i - NS) * CC;
    float4 myp = ((const float4*)prow)[lane];
    const int im = i & (NS - 1);
    const int li = label[im];
    float rowsum = 0.f;
    #pragma unroll
    for (int r = 0; r < 10; r++) {
        int j = rc[r];
        int jm = j & (NS - 1);
        if (li == label[jm] && li != -1 && im != jm) {
            const float* pr = (j < NS) ? zip + (size_t)j * CC : zjp + (size_t)(j - NS) * CC;
            float4 q4 = ((const float4*)pr)[lane];
            float part = myp.x * q4.x + myp.y * q4.y + myp.z * q4.z + myp.w * q4.w;
            #pragma unroll
            for (int o = 16; o; o >>= 1) part += __shfl_xor_sync(0xffffffffu, part, o);
            float pd = sqrtf(fmaxf(rd[r], 0.f));
            float ww = 1.f - fminf(fmaxf((pd - radius) / radius, 0.f), 1.f);
            rowsum += ww * part;
        }
    }
    if (lane == 0) g_part[i] = rowsum;

    // ---- last-block deterministic reduction ----
    __shared__ int s_last;
    __shared__ float s_red[256];
    __threadfence();
    __syncthreads();
    if (threadIdx.x == 0) s_last = (atomicAdd(&g_ctr, 1) == gridDim.x - 1) ? 1 : 0;
    __syncthreads();
    if (s_last) {
        int tdx = threadIdx.x;
        float a = 0.f;
        #pragma unroll
        for (int q = 0; q < 16; q++) a += g_part[tdx + 256 * q];
        s_red[tdx] = a;
        __syncthreads();
        for (int o = 128; o; o >>= 1) {
            if (tdx < o) s_red[tdx] += s_red[tdx + o];
            __syncthreads();
        }
        if (tdx == 0) out[0] = s_red[0] * (1.0f / ((float)BB * (float)BB));
    }
}

// ---------------------------------------------------------------------------
extern "C" void kernel_launch(void* const* d_in, const int* in_sizes, int n_in,
                              void* d_out, int out_size) {
    const float* z_i = (const float*)d_in[0];
    const float* z_j = (const float*)d_in[1];
    const float* z_i_prob = (const float*)d_in[2];
    const float* z_j_prob = (const float*)d_in[3];
    const int* pseudo_label = (const int*)d_in[4];
    float* out = (float*)d_out;

    cudaFuncSetAttribute(gemm_select_kernel,
                         cudaFuncAttributeMaxDynamicSharedMemorySize, DYN_SMEM);

    convsq_kernel<<<BB / 8, 256>>>(z_i, z_j);
    gemm_select_kernel<<<NTILES, 256, DYN_SMEM>>>();
    merge_loss_kernel<<<BB / 8, 256>>>(z_i, z_j, z_i_prob, z_j_prob, pseudo_label, out);
}

// round 13
// speedup vs baseline: 1.3795x; 1.3768x over previous
#include <cuda_runtime.h>
#include <cuda_bf16.h>
#include <math.h>
#include <float.h>
#include <stdint.h>

// Problem constants
#define NS 2048        // n
#define BB 4096        // 2n
#define DD 512         // feature dim
#define CC 128         // num classes
#define KC 12          // candidates per (row,tile) and final candidate count
#define NT_COL 32      // 4096/128 column tiles
#define NTILES 528     // upper-triangular 32x32 tile count

// Scratch (allocation-free rule: __device__ globals)
__device__ float g_sq[BB];                                          // exact fp32 row squared norms
__device__ float g_part[BB];                                        // per-row partial sums
__device__ int g_ctr;                                               // last-block counter
__device__ __align__(16) __nv_bfloat16 g_fb[(size_t)BB * DD];       // 4 MB bf16 feats
__device__ __align__(16) uint32_t g_cand[(size_t)BB * NT_COL * KC]; // 6.3 MB packed keys

// ---------------------------------------------------------------------------
// helpers
// ---------------------------------------------------------------------------
__device__ __forceinline__ uint32_t smem_u32(const void* p) {
    uint32_t a;
    asm("{ .reg .u64 t; cvta.to.shared.u64 t, %1; cvt.u32.u64 %0, t; }" : "=r"(a) : "l"(p));
    return a;
}
__device__ __forceinline__ void cp16(uint32_t dst, const void* src) {
    asm volatile("cp.async.cg.shared.global [%0], [%1], 16;" :: "r"(dst), "l"(src) : "memory");
}
#define CP_COMMIT() asm volatile("cp.async.commit_group;" ::: "memory")
#define CP_WAIT(N)  asm volatile("cp.async.wait_group %0;" :: "n"(N) : "memory")

#define LDSM_X4(d, addr) \
    asm volatile("ldmatrix.sync.aligned.m8n8.x4.shared.b16 {%0,%1,%2,%3}, [%4];" \
                 : "=r"((d)[0]), "=r"((d)[1]), "=r"((d)[2]), "=r"((d)[3]) : "r"(addr))

#define MMA16816(c, a, b0, b1) \
    asm volatile("mma.sync.aligned.m16n8k16.row.col.f32.bf16.bf16.f32 " \
                 "{%0,%1,%2,%3}, {%4,%5,%6,%7}, {%8,%9}, {%0,%1,%2,%3};" \
                 : "+f"((c)[0]), "+f"((c)[1]), "+f"((c)[2]), "+f"((c)[3]) \
                 : "r"((a)[0]), "r"((a)[1]), "r"((a)[2]), "r"((a)[3]), "r"(b0), "r"(b1))

// monotone float->uint order map, low 7 bits replaced by tile-local index
__device__ __forceinline__ uint32_t pack_key(float s, int idx) {
    uint32_t u = __float_as_uint(s);
    u ^= ((uint32_t)((int32_t)u >> 31)) | 0x80000000u;
    return (u & 0xFFFFFF80u) | (uint32_t)idx;
}

// ---------------------------------------------------------------------------
// Kernel 0: fused fp32->bf16 conversion + exact fp32 row norms. Warp per row.
// Also resets the last-block counter (graph-replay safe).
// ---------------------------------------------------------------------------
__global__ void convsq_kernel(const float* __restrict__ zi, const float* __restrict__ zj) {
    if (blockIdx.x == 0 && threadIdx.x == 0) g_ctr = 0;
    int w = (blockIdx.x * blockDim.x + threadIdx.x) >> 5;
    int lane = threadIdx.x & 31;
    if (w >= BB) return;
    const float* p = (w < NS) ? zi + (size_t)w * DD : zj + (size_t)(w - NS) * DD;
    const float4* p4 = (const float4*)p;
    __nv_bfloat162* dst = (__nv_bfloat162*)(g_fb + (size_t)w * DD);
    float s = 0.f;
    #pragma unroll
    for (int k = lane; k < DD / 4; k += 32) {
        float4 v = p4[k];
        s += v.x * v.x + v.y * v.y + v.z * v.z + v.w * v.w;
        dst[2 * k]     = __floats2bfloat162_rn(v.x, v.y);
        dst[2 * k + 1] = __floats2bfloat162_rn(v.z, v.w);
    }
    #pragma unroll
    for (int o = 16; o; o >>= 1) s += __shfl_xor_sync(0xffffffffu, s, o);
    if (lane == 0) g_sq[w] = s;
}

// ---------------------------------------------------------------------------
// Kernel 2: SYMMETRIC bf16 mma.sync GEMM — 528 upper-tri 128x128 tiles,
// R9 2-stage double-buffered mainloop. Epilogue stages raw dots, then
// THREAD-PER-ROW (tid<128) + THREAD-PER-COL (tid>=128) top-12 selection,
// both halves concurrent, no warp merges or extraction rounds.
// ---------------------------------------------------------------------------
#define KT    16            // 512 / 32 k-tiles
#define SROW  40            // smem row stride in bf16 elems (80 B)
#define SBUF  (128 * SROW)  // elems per tile buffer (5120)
#define STG_STRIDE 132      // stage row stride in words
#define DYN_SMEM (128 * STG_STRIDE * 4)   // 67584 B (covers the 40960 B A/B bufs)

__global__ void __launch_bounds__(256, 2) gemm_select_kernel() {
    extern __shared__ __align__(16) char dsm[];
    __shared__ float s_sqm[128], s_sqn[128];

    __nv_bfloat16* As = (__nv_bfloat16*)dsm;             // [2][SBUF]
    __nv_bfloat16* Bs = (__nv_bfloat16*)(dsm + 20480);   // [2][SBUF]
    float* stg = (float*)dsm;                            // [128][132] raw dots

    const int tid = threadIdx.x;
    const int lane = tid & 31;
    const int wid = tid >> 5;
    const int wy = wid >> 2;
    const int wx = wid & 3;

    // upper-tri tile map: blockIdx.x -> (bi, bj), bj >= bi
    int t = blockIdx.x;
    int bi = 0;
    while (t >= NT_COL - bi) { t -= NT_COL - bi; ++bi; }
    const int bj = bi + t;
    const int m0 = bi << 7;
    const int n0 = bj << 7;
    const bool diag = (bi == bj);

    if (tid < 128) { s_sqm[tid] = g_sq[m0 + tid]; s_sqn[tid] = g_sq[n0 + tid]; }

    const int lr = tid >> 1;
    const int lu = (tid & 1) * 16;
    const uint32_t sA = smem_u32(As);
    const uint32_t sB = smem_u32(Bs);
    const uint32_t sdoff = (uint32_t)(lr * SROW + lu) * 2;
    const __nv_bfloat16* gA = g_fb + (size_t)(m0 + lr) * DD + lu;
    const __nv_bfloat16* gB = g_fb + (size_t)(n0 + lr) * DD + lu;

    const int rowA = wy * 64 + (lane & 7) + ((lane >> 3) & 1) * 8;
    const int colA = (lane >> 4) * 8;
    const int rowB = wx * 32 + (lane & 7) + (lane >> 4) * 8;
    const int colB = ((lane >> 3) & 1) * 8;

    float acc[4][4][4];
    #pragma unroll
    for (int i = 0; i < 4; i++)
        #pragma unroll
        for (int j = 0; j < 4; j++)
            #pragma unroll
            for (int q = 0; q < 4; q++) acc[i][j][q] = 0.f;

    {
        cp16(sA + sdoff, gA); cp16(sA + sdoff + 16, gA + 8);
        cp16(sB + sdoff, gB); cp16(sB + sdoff + 16, gB + 8);
        CP_COMMIT();
    }

    for (int kt = 0; kt < KT; ++kt) {
        const int buf = kt & 1;
        if (kt + 1 < KT) {
            const uint32_t boff = (uint32_t)(buf ^ 1) * (SBUF * 2);
            const __nv_bfloat16* pa = gA + (kt + 1) * 32;
            const __nv_bfloat16* pb = gB + (kt + 1) * 32;
            cp16(sA + boff + sdoff, pa); cp16(sA + boff + sdoff + 16, pa + 8);
            cp16(sB + boff + sdoff, pb); cp16(sB + boff + sdoff + 16, pb + 8);
            CP_COMMIT();
            CP_WAIT(1);
        } else {
            CP_WAIT(0);
        }
        __syncthreads();

        const uint32_t ab = sA + (uint32_t)buf * (SBUF * 2);
        const uint32_t bb = sB + (uint32_t)buf * (SBUF * 2);
        #pragma unroll
        for (int ks = 0; ks < 2; ++ks) {
            uint32_t a[4][4], b[2][4];
            #pragma unroll
            for (int mi = 0; mi < 4; mi++)
                LDSM_X4(a[mi], ab + (uint32_t)((rowA + mi * 16) * SROW + ks * 16 + colA) * 2);
            #pragma unroll
            for (int ng = 0; ng < 2; ng++)
                LDSM_X4(b[ng], bb + (uint32_t)((rowB + ng * 16) * SROW + ks * 16 + colB) * 2);
            #pragma unroll
            for (int mi = 0; mi < 4; mi++)
                #pragma unroll
                for (int nb = 0; nb < 4; nb++)
                    MMA16816(acc[mi][nb], a[mi], b[nb >> 1][(nb & 1) * 2], b[nb >> 1][(nb & 1) * 2 + 1]);
        }
        __syncthreads();
    }
    // A/B smem dead; stage raw dot values so acc registers die here.

    {
        const int er = (lane >> 2);
        const int ec = wx * 32 + (lane & 3) * 2;
        #pragma unroll
        for (int mi = 0; mi < 4; mi++) {
            const int ra = wy * 64 + mi * 16 + er;
            const int rb = ra + 8;
            #pragma unroll
            for (int nb = 0; nb < 4; nb++) {
                const int cc = ec + nb * 8;
                stg[ra * STG_STRIDE + cc]     = acc[mi][nb][0];
                stg[ra * STG_STRIDE + cc + 1] = acc[mi][nb][1];
                stg[rb * STG_STRIDE + cc]     = acc[mi][nb][2];
                stg[rb * STG_STRIDE + cc + 1] = acc[mi][nb][3];
            }
        }
    }
    __syncthreads();

    // ---- selection: thread-per-row (tid<128) and thread-per-col (tid>=128) ----
    {
        const int idx = tid & 127;
        uint32_t keys[KC];
        #pragma unroll
        for (int q = 0; q < KC; q++) keys[q] = 0xFFFFFFFFu;

        if (tid < 128) {
            // ROW PASS: rank cols (block bj) for m-row idx
            const float4* srow = (const float4*)(stg + idx * STG_STRIDE);
            #pragma unroll 4
            for (int q = 0; q < 32; ++q) {
                float4 d4 = srow[q];
                float dv[4] = {d4.x, d4.y, d4.z, d4.w};
                #pragma unroll
                for (int k = 0; k < 4; k++) {
                    const int c = q * 4 + k;
                    uint32_t u = pack_key(fmaf(-2.f, dv[k], s_sqn[c]), c);
                    if (diag && c == idx) u = 0xFFFFFFFFu;
                    if (u < keys[KC - 1]) {
                        keys[KC - 1] = u;
                        #pragma unroll
                        for (int s = KC - 1; s >= 1; s--) {
                            if (keys[s] < keys[s - 1]) {
                                uint32_t tt = keys[s]; keys[s] = keys[s - 1]; keys[s - 1] = tt;
                            }
                        }
                    }
                }
            }
            uint32_t* crow = g_cand + ((size_t)(m0 + idx) * NT_COL + bj) * KC;
            #pragma unroll
            for (int r = 0; r < KC; ++r) crow[r] = keys[r];
        } else if (!diag) {
            // COL PASS: rank rows (block bi) for n-col idx; 4-deep batched loads
            #pragma unroll 2
            for (int rb = 0; rb < 32; ++rb) {
                float dd[4];
                #pragma unroll
                for (int u2 = 0; u2 < 4; ++u2)
                    dd[u2] = stg[(rb * 4 + u2) * STG_STRIDE + idx];
                #pragma unroll
                for (int u2 = 0; u2 < 4; ++u2) {
                    const int r = rb * 4 + u2;
                    uint32_t uk = pack_key(fmaf(-2.f, dd[u2], s_sqm[r]), r);
                    if (uk < keys[KC - 1]) {
                        keys[KC - 1] = uk;
                        #pragma unroll
                        for (int s = KC - 1; s >= 1; s--) {
                            if (keys[s] < keys[s - 1]) {
                                uint32_t tt = keys[s]; keys[s] = keys[s - 1]; keys[s - 1] = tt;
                            }
                        }
                    }
                }
            }
            uint32_t* crow = g_cand + ((size_t)(n0 + idx) * NT_COL + bi) * KC;
            #pragma unroll
            for (int r = 0; r < KC; ++r) crow[r] = keys[r];
        }
    }
}

// ---------------------------------------------------------------------------
// Kernel 3: merge 32x12 packed per-tile candidates -> approx top-12 -> exact
// fp32 rescore -> exact top-10 -> weights, masked prob-dots. Warp per row.
// Last-arriving block performs the deterministic final reduction.
// ---------------------------------------------------------------------------
__global__ void merge_loss_kernel(const float* __restrict__ zi,
                                  const float* __restrict__ zj,
                                  const float* __restrict__ zip,
                                  const float* __restrict__ zjp,
                                  const int* __restrict__ label,
                                  float* __restrict__ out) {
    int w = (blockIdx.x * blockDim.x + threadIdx.x) >> 5;
    int lane = threadIdx.x & 31;
    const int i = w;
    const uint32_t* crow = g_cand + (size_t)i * (NT_COL * KC);

    // per-lane sorted top-12 over its 12 assigned candidates
    uint32_t v[KC]; int c[KC];
    #pragma unroll
    for (int q = 0; q < KC; q++) { v[q] = 0xFFFFFFFFu; c[q] = 0x7fffffff; }
    #pragma unroll
    for (int t = 0; t < KC; ++t) {
        const int e = t * 32 + lane;          // 0..383
        const uint32_t k = crow[e];
        const int tile = e / KC;
        const int gcol = tile * 128 + (int)(k & 127u);
        if (k < v[KC - 1]) {
            v[KC - 1] = k; c[KC - 1] = gcol;
            #pragma unroll
            for (int q = KC - 1; q >= 1; q--) {
                if (v[q] < v[q - 1]) {
                    uint32_t tv = v[q]; v[q] = v[q - 1]; v[q - 1] = tv;
                    int tc = c[q]; c[q] = c[q - 1]; c[q - 1] = tc;
                }
            }
        }
    }

    // full-warp merge: 12 rounds of argmin-extract (R9 form)
    int rc[KC];
    #pragma unroll
    for (int r = 0; r < KC; r++) {
        uint32_t mv = v[0]; int mc = c[0];
        #pragma unroll
        for (int o = 16; o; o >>= 1) {
            uint32_t ov = __shfl_down_sync(0xffffffffu, mv, o);
            int oc = __shfl_down_sync(0xffffffffu, mc, o);
            if (ov < mv || (ov == mv && oc < mc)) { mv = ov; mc = oc; }
        }
        mc = __shfl_sync(0xffffffffu, mc, 0);
        rc[r] = mc;
        if (c[0] == mc) {
            #pragma unroll
            for (int q = 0; q < KC - 1; q++) { v[q] = v[q + 1]; c[q] = c[q + 1]; }
            v[KC - 1] = 0xFFFFFFFFu; c[KC - 1] = 0x7fffffff;
        }
    }

    // exact fp32 rescore of the 12 candidates (sequential, low reg pressure)
    const float* fip = (i < NS) ? zi + (size_t)i * DD : zj + (size_t)(i - NS) * DD;
    float4 fi[4];
    #pragma unroll
    for (int q = 0; q < 4; q++) fi[q] = ((const float4*)fip)[lane + 32 * q];
    const float sqi = g_sq[i];

    float rd[KC];
    #pragma unroll
    for (int r = 0; r < KC; r++) {
        int j = rc[r];
        const float* fjp = (j < NS) ? zi + (size_t)j * DD : zj + (size_t)(j - NS) * DD;
        float s = 0.f;
        #pragma unroll
        for (int q = 0; q < 4; q++) {
            float4 fj = ((const float4*)fjp)[lane + 32 * q];
            s += fi[q].x * fj.x + fi[q].y * fj.y + fi[q].z * fj.z + fi[q].w * fj.w;
        }
        #pragma unroll
        for (int o = 16; o; o >>= 1) s += __shfl_xor_sync(0xffffffffu, s, o);
        rd[r] = sqi + g_sq[j] - 2.f * s;           // exact d2 (all lanes agree)
    }

    // per-lane redundant sort of 12 (ascending d2, index tiebreak)
    #pragma unroll
    for (int a = 1; a < KC; a++) {
        float dv = rd[a]; int ci = rc[a];
        int b = a;
        while (b > 0 && (rd[b - 1] > dv || (rd[b - 1] == dv && rc[b - 1] > ci))) {
            rd[b] = rd[b - 1]; rc[b] = rc[b - 1]; --b;
        }
        rd[b] = dv; rc[b] = ci;
    }

    // weights + masked prob-dots over exact top-10
    float radius = sqrtf(fmaxf(rd[0], 0.f));
    const float* prow = (i < NS) ? zip + (size_t)i * CC : zjp + (size_t)(i - NS) * CC;
    float4 myp = ((const float4*)prow)[lane];
    const int im = i & (NS - 1);
    const int li = label[im];
    float rowsum = 0.f;
    #pragma unroll
    for (int r = 0; r < 10; r++) {
        int j = rc[r];
        int jm = j & (NS - 1);
        if (li == label[jm] && li != -1 && im != jm) {
            const float* pr = (j < NS) ? zip + (size_t)j * CC : zjp + (size_t)(j - NS) * CC;
            float4 q4 = ((const float4*)pr)[lane];
            float part = myp.x * q4.x + myp.y * q4.y + myp.z * q4.z + myp.w * q4.w;
            #pragma unroll
            for (int o = 16; o; o >>= 1) part += __shfl_xor_sync(0xffffffffu, part, o);
            float pd = sqrtf(fmaxf(rd[r], 0.f));
            float ww = 1.f - fminf(fmaxf((pd - radius) / radius, 0.f), 1.f);
            rowsum += ww * part;
        }
    }
    if (lane == 0) g_part[i] = rowsum;

    // ---- last-block deterministic reduction ----
    __shared__ int s_last;
    __shared__ float s_red[256];
    __threadfence();
    __syncthreads();
    if (threadIdx.x == 0) s_last = (atomicAdd(&g_ctr, 1) == gridDim.x - 1) ? 1 : 0;
    __syncthreads();
    if (s_last) {
        int tdx = threadIdx.x;
        float a = 0.f;
        #pragma unroll
        for (int q = 0; q < 16; q++) a += g_part[tdx + 256 * q];
        s_red[tdx] = a;
        __syncthreads();
        for (int o = 128; o; o >>= 1) {
            if (tdx < o) s_red[tdx] += s_red[tdx + o];
            __syncthreads();
        }
        if (tdx == 0) out[0] = s_red[0] * (1.0f / ((float)BB * (float)BB));
    }
}

// ---------------------------------------------------------------------------
extern "C" void kernel_launch(void* const* d_in, const int* in_sizes, int n_in,
                              void* d_out, int out_size) {
    const float* z_i = (const float*)d_in[0];
    const float* z_j = (const float*)d_in[1];
    const float* z_i_prob = (const float*)d_in[2];
    const float* z_j_prob = (const float*)d_in[3];
    const int* pseudo_label = (const int*)d_in[4];
    float* out = (float*)d_out;

    cudaFuncSetAttribute(gemm_select_kernel,
                         cudaFuncAttributeMaxDynamicSharedMemorySize, DYN_SMEM);

    convsq_kernel<<<BB / 8, 256>>>(z_i, z_j);
    gemm_select_kernel<<<NTILES, 256, DYN_SMEM>>>();
    merge_loss_kernel<<<BB / 8, 256>>>(z_i, z_j, z_i_prob, z_j_prob, pseudo_label, out);
}

// round 14
// speedup vs baseline: 1.4522x; 1.0527x over previous
#include <cuda_runtime.h>
#include <cuda_bf16.h>
#include <math.h>
#include <float.h>
#include <stdint.h>

// Problem constants
#define NS 2048        // n
#define BB 4096        // 2n
#define DD 512         // feature dim
#define CC 128         // num classes
#define KC 12          // candidates per (row,tile) and final candidate count
#define NT_COL 32      // 4096/128 column tiles
#define NTILES 528     // upper-triangular 32x32 tile count

// Scratch (allocation-free rule: __device__ globals)
__device__ float g_sq[BB];                                          // exact fp32 row squared norms
__device__ float g_part[BB];                                        // per-row partial sums
__device__ int g_ctr;                                               // last-block counter
__device__ __align__(16) __nv_bfloat16 g_fb[(size_t)BB * DD];       // 4 MB bf16 feats
__device__ __align__(16) uint32_t g_cand[(size_t)BB * NT_COL * KC]; // 6.3 MB packed keys

// ---------------------------------------------------------------------------
// helpers
// ---------------------------------------------------------------------------
__device__ __forceinline__ uint32_t smem_u32(const void* p) {
    uint32_t a;
    asm("{ .reg .u64 t; cvta.to.shared.u64 t, %1; cvt.u32.u64 %0, t; }" : "=r"(a) : "l"(p));
    return a;
}
__device__ __forceinline__ void cp16(uint32_t dst, const void* src) {
    asm volatile("cp.async.cg.shared.global [%0], [%1], 16;" :: "r"(dst), "l"(src) : "memory");
}
#define CP_COMMIT() asm volatile("cp.async.commit_group;" ::: "memory")
#define CP_WAIT(N)  asm volatile("cp.async.wait_group %0;" :: "n"(N) : "memory")

#define LDSM_X4(d, addr) \
    asm volatile("ldmatrix.sync.aligned.m8n8.x4.shared.b16 {%0,%1,%2,%3}, [%4];" \
                 : "=r"((d)[0]), "=r"((d)[1]), "=r"((d)[2]), "=r"((d)[3]) : "r"(addr))

#define MMA16816(c, a, b0, b1) \
    asm volatile("mma.sync.aligned.m16n8k16.row.col.f32.bf16.bf16.f32 " \
                 "{%0,%1,%2,%3}, {%4,%5,%6,%7}, {%8,%9}, {%0,%1,%2,%3};" \
                 : "+f"((c)[0]), "+f"((c)[1]), "+f"((c)[2]), "+f"((c)[3]) \
                 : "r"((a)[0]), "r"((a)[1]), "r"((a)[2]), "r"((a)[3]), "r"(b0), "r"(b1))

// monotone float->uint order map, low 7 bits replaced by tile-local index
__device__ __forceinline__ uint32_t pack_key(float s, int idx) {
    uint32_t u = __float_as_uint(s);
    u ^= ((uint32_t)((int32_t)u >> 31)) | 0x80000000u;
    return (u & 0xFFFFFF80u) | (uint32_t)idx;
}

// ---------------------------------------------------------------------------
// Kernel 0: fused fp32->bf16 conversion + exact fp32 row norms. Warp per row.
// Also resets the last-block counter (graph-replay safe).
// ---------------------------------------------------------------------------
__global__ void convsq_kernel(const float* __restrict__ zi, const float* __restrict__ zj) {
    if (blockIdx.x == 0 && threadIdx.x == 0) g_ctr = 0;
    int w = (blockIdx.x * blockDim.x + threadIdx.x) >> 5;
    int lane = threadIdx.x & 31;
    if (w >= BB) return;
    const float* p = (w < NS) ? zi + (size_t)w * DD : zj + (size_t)(w - NS) * DD;
    const float4* p4 = (const float4*)p;
    __nv_bfloat162* dst = (__nv_bfloat162*)(g_fb + (size_t)w * DD);
    float s = 0.f;
    #pragma unroll
    for (int k = lane; k < DD / 4; k += 32) {
        float4 v = p4[k];
        s += v.x * v.x + v.y * v.y + v.z * v.z + v.w * v.w;
        dst[2 * k]     = __floats2bfloat162_rn(v.x, v.y);
        dst[2 * k + 1] = __floats2bfloat162_rn(v.z, v.w);
    }
    #pragma unroll
    for (int o = 16; o; o >>= 1) s += __shfl_xor_sync(0xffffffffu, s, o);
    if (lane == 0) g_sq[w] = s;
}

// ---------------------------------------------------------------------------
// Kernel 2: SYMMETRIC bf16 mma.sync GEMM — 528 upper-tri 128x128 tiles,
// 2-stage double-buffered mainloop. Epilogue stages raw dots, then
// thread-per-row (tid<128) + thread-per-col (tid>=128) top-12 selection.
// (unchanged from R13 — the 95.2us baseline)
// ---------------------------------------------------------------------------
#define KT    16            // 512 / 32 k-tiles
#define SROW  40            // smem row stride in bf16 elems (80 B)
#define SBUF  (128 * SROW)  // elems per tile buffer (5120)
#define STG_STRIDE 132      // stage row stride in words
#define DYN_SMEM (128 * STG_STRIDE * 4)   // 67584 B (covers the 40960 B A/B bufs)

__global__ void __launch_bounds__(256, 2) gemm_select_kernel() {
    extern __shared__ __align__(16) char dsm[];
    __shared__ float s_sqm[128], s_sqn[128];

    __nv_bfloat16* As = (__nv_bfloat16*)dsm;             // [2][SBUF]
    __nv_bfloat16* Bs = (__nv_bfloat16*)(dsm + 20480);   // [2][SBUF]
    float* stg = (float*)dsm;                            // [128][132] raw dots

    const int tid = threadIdx.x;
    const int lane = tid & 31;
    const int wid = tid >> 5;
    const int wy = wid >> 2;
    const int wx = wid & 3;

    // upper-tri tile map: blockIdx.x -> (bi, bj), bj >= bi
    int t = blockIdx.x;
    int bi = 0;
    while (t >= NT_COL - bi) { t -= NT_COL - bi; ++bi; }
    const int bj = bi + t;
    const int m0 = bi << 7;
    const int n0 = bj << 7;
    const bool diag = (bi == bj);

    if (tid < 128) { s_sqm[tid] = g_sq[m0 + tid]; s_sqn[tid] = g_sq[n0 + tid]; }

    const int lr = tid >> 1;
    const int lu = (tid & 1) * 16;
    const uint32_t sA = smem_u32(As);
    const uint32_t sB = smem_u32(Bs);
    const uint32_t sdoff = (uint32_t)(lr * SROW + lu) * 2;
    const __nv_bfloat16* gA = g_fb + (size_t)(m0 + lr) * DD + lu;
    const __nv_bfloat16* gB = g_fb + (size_t)(n0 + lr) * DD + lu;

    const int rowA = wy * 64 + (lane & 7) + ((lane >> 3) & 1) * 8;
    const int colA = (lane >> 4) * 8;
    const int rowB = wx * 32 + (lane & 7) + (lane >> 4) * 8;
    const int colB = ((lane >> 3) & 1) * 8;

    float acc[4][4][4];
    #pragma unroll
    for (int i = 0; i < 4; i++)
        #pragma unroll
        for (int j = 0; j < 4; j++)
            #pragma unroll
            for (int q = 0; q < 4; q++) acc[i][j][q] = 0.f;

    {
        cp16(sA + sdoff, gA); cp16(sA + sdoff + 16, gA + 8);
        cp16(sB + sdoff, gB); cp16(sB + sdoff + 16, gB + 8);
        CP_COMMIT();
    }

    for (int kt = 0; kt < KT; ++kt) {
        const int buf = kt & 1;
        if (kt + 1 < KT) {
            const uint32_t boff = (uint32_t)(buf ^ 1) * (SBUF * 2);
            const __nv_bfloat16* pa = gA + (kt + 1) * 32;
            const __nv_bfloat16* pb = gB + (kt + 1) * 32;
            cp16(sA + boff + sdoff, pa); cp16(sA + boff + sdoff + 16, pa + 8);
            cp16(sB + boff + sdoff, pb); cp16(sB + boff + sdoff + 16, pb + 8);
            CP_COMMIT();
            CP_WAIT(1);
        } else {
            CP_WAIT(0);
        }
        __syncthreads();

        const uint32_t ab = sA + (uint32_t)buf * (SBUF * 2);
        const uint32_t bb = sB + (uint32_t)buf * (SBUF * 2);
        #pragma unroll
        for (int ks = 0; ks < 2; ++ks) {
            uint32_t a[4][4], b[2][4];
            #pragma unroll
            for (int mi = 0; mi < 4; mi++)
                LDSM_X4(a[mi], ab + (uint32_t)((rowA + mi * 16) * SROW + ks * 16 + colA) * 2);
            #pragma unroll
            for (int ng = 0; ng < 2; ng++)
                LDSM_X4(b[ng], bb + (uint32_t)((rowB + ng * 16) * SROW + ks * 16 + colB) * 2);
            #pragma unroll
            for (int mi = 0; mi < 4; mi++)
                #pragma unroll
                for (int nb = 0; nb < 4; nb++)
                    MMA16816(acc[mi][nb], a[mi], b[nb >> 1][(nb & 1) * 2], b[nb >> 1][(nb & 1) * 2 + 1]);
        }
        __syncthreads();
    }
    // A/B smem dead; stage raw dot values so acc registers die here.

    {
        const int er = (lane >> 2);
        const int ec = wx * 32 + (lane & 3) * 2;
        #pragma unroll
        for (int mi = 0; mi < 4; mi++) {
            const int ra = wy * 64 + mi * 16 + er;
            const int rb = ra + 8;
            #pragma unroll
            for (int nb = 0; nb < 4; nb++) {
                const int cc = ec + nb * 8;
                stg[ra * STG_STRIDE + cc]     = acc[mi][nb][0];
                stg[ra * STG_STRIDE + cc + 1] = acc[mi][nb][1];
                stg[rb * STG_STRIDE + cc]     = acc[mi][nb][2];
                stg[rb * STG_STRIDE + cc + 1] = acc[mi][nb][3];
            }
        }
    }
    __syncthreads();

    // ---- selection: thread-per-row (tid<128) and thread-per-col (tid>=128) ----
    {
        const int idx = tid & 127;
        uint32_t keys[KC];
        #pragma unroll
        for (int q = 0; q < KC; q++) keys[q] = 0xFFFFFFFFu;

        if (tid < 128) {
            // ROW PASS: rank cols (block bj) for m-row idx
            const float4* srow = (const float4*)(stg + idx * STG_STRIDE);
            #pragma unroll 4
            for (int q = 0; q < 32; ++q) {
                float4 d4 = srow[q];
                float dv[4] = {d4.x, d4.y, d4.z, d4.w};
                #pragma unroll
                for (int k = 0; k < 4; k++) {
                    const int c = q * 4 + k;
                    uint32_t u = pack_key(fmaf(-2.f, dv[k], s_sqn[c]), c);
                    if (diag && c == idx) u = 0xFFFFFFFFu;
                    if (u < keys[KC - 1]) {
                        keys[KC - 1] = u;
                        #pragma unroll
                        for (int s = KC - 1; s >= 1; s--) {
                            if (keys[s] < keys[s - 1]) {
                                uint32_t tt = keys[s]; keys[s] = keys[s - 1]; keys[s - 1] = tt;
                            }
                        }
                    }
                }
            }
            uint32_t* crow = g_cand + ((size_t)(m0 + idx) * NT_COL + bj) * KC;
            #pragma unroll
            for (int r = 0; r < KC; ++r) crow[r] = keys[r];
        } else if (!diag) {
            // COL PASS: rank rows (block bi) for n-col idx; 4-deep batched loads
            #pragma unroll 2
            for (int rb = 0; rb < 32; ++rb) {
                float dd[4];
                #pragma unroll
                for (int u2 = 0; u2 < 4; ++u2)
                    dd[u2] = stg[(rb * 4 + u2) * STG_STRIDE + idx];
                #pragma unroll
                for (int u2 = 0; u2 < 4; ++u2) {
                    const int r = rb * 4 + u2;
                    uint32_t uk = pack_key(fmaf(-2.f, dd[u2], s_sqm[r]), r);
                    if (uk < keys[KC - 1]) {
                        keys[KC - 1] = uk;
                        #pragma unroll
                        for (int s = KC - 1; s >= 1; s--) {
                            if (keys[s] < keys[s - 1]) {
                                uint32_t tt = keys[s]; keys[s] = keys[s - 1]; keys[s - 1] = tt;
                            }
                        }
                    }
                }
            }
            uint32_t* crow = g_cand + ((size_t)(n0 + idx) * NT_COL + bi) * KC;
            #pragma unroll
            for (int r = 0; r < KC; ++r) crow[r] = keys[r];
        }
    }
}

// ---------------------------------------------------------------------------
// Kernel 3: merge. Lane = tile (12 keys arrive SORTED from the gemm epilogue,
// loaded as 3x uint4 -> no insertion). 12 extraction rounds with single-value
// shfl-min + ballot (owner lane encodes the tile). Rescore processes 2
// candidates per round for load MLP + interleaved reduction chains.
// ---------------------------------------------------------------------------
__global__ void merge_loss_kernel(const float* __restrict__ zi,
                                  const float* __restrict__ zj,
                                  const float* __restrict__ zip,
                                  const float* __restrict__ zjp,
                                  const int* __restrict__ label,
                                  float* __restrict__ out) {
    int w = (blockIdx.x * blockDim.x + threadIdx.x) >> 5;
    int lane = threadIdx.x & 31;
    const int i = w;

    // lane = tile: load that tile's 12 sorted keys (3x uint4, coalesced)
    const uint4* cr4 = (const uint4*)(g_cand + (size_t)i * (NT_COL * KC)) + lane * 3;
    uint4 a0 = cr4[0], a1 = cr4[1], a2 = cr4[2];
    uint32_t v[KC] = {a0.x, a0.y, a0.z, a0.w, a1.x, a1.y, a1.z, a1.w,
                      a2.x, a2.y, a2.z, a2.w};

    // 12 rounds of single-value warp-min extraction; gcol from owner lane
    int rc[KC];
    #pragma unroll
    for (int r = 0; r < KC; r++) {
        uint32_t mv = v[0];
        #pragma unroll
        for (int o = 16; o; o >>= 1) {
            uint32_t ov = __shfl_xor_sync(0xffffffffu, mv, o);
            mv = (ov < mv) ? ov : mv;
        }
        unsigned own = __ballot_sync(0xffffffffu, v[0] == mv);
        int leader = __ffs((int)own) - 1;
        rc[r] = leader * 128 + (int)(mv & 127u);
        if (lane == leader) {
            #pragma unroll
            for (int q = 0; q < KC - 1; q++) v[q] = v[q + 1];
            v[KC - 1] = 0xFFFFFFFFu;
        }
    }

    // exact fp32 rescore — 2 candidates per round (8 loads in flight,
    // interleaved reduction chains)
    const float* fip = (i < NS) ? zi + (size_t)i * DD : zj + (size_t)(i - NS) * DD;
    float4 fi[4];
    #pragma unroll
    for (int q = 0; q < 4; q++) fi[q] = ((const float4*)fip)[lane + 32 * q];
    const float sqi = g_sq[i];

    float rd[KC];
    #pragma unroll
    for (int rp2 = 0; rp2 < KC; rp2 += 2) {
        const int j0 = rc[rp2], j1 = rc[rp2 + 1];
        const float* f0p = (j0 < NS) ? zi + (size_t)j0 * DD : zj + (size_t)(j0 - NS) * DD;
        const float* f1p = (j1 < NS) ? zi + (size_t)j1 * DD : zj + (size_t)(j1 - NS) * DD;
        float s0 = 0.f, s1 = 0.f;
        #pragma unroll
        for (int q = 0; q < 4; q++) {
            float4 u0 = ((const float4*)f0p)[lane + 32 * q];
            float4 u1 = ((const float4*)f1p)[lane + 32 * q];
            s0 += fi[q].x * u0.x + fi[q].y * u0.y + fi[q].z * u0.z + fi[q].w * u0.w;
            s1 += fi[q].x * u1.x + fi[q].y * u1.y + fi[q].z * u1.z + fi[q].w * u1.w;
        }
        #pragma unroll
        for (int o = 16; o; o >>= 1) {
            s0 += __shfl_xor_sync(0xffffffffu, s0, o);
            s1 += __shfl_xor_sync(0xffffffffu, s1, o);
        }
        rd[rp2]     = sqi + g_sq[j0] - 2.f * s0;   // exact d2 (all lanes agree)
        rd[rp2 + 1] = sqi + g_sq[j1] - 2.f * s1;
    }

    // per-lane redundant sort of 12 (ascending d2, index tiebreak)
    #pragma unroll
    for (int a = 1; a < KC; a++) {
        float dv = rd[a]; int ci = rc[a];
        int b = a;
        while (b > 0 && (rd[b - 1] > dv || (rd[b - 1] == dv && rc[b - 1] > ci))) {
            rd[b] = rd[b - 1]; rc[b] = rc[b - 1]; --b;
        }
        rd[b] = dv; rc[b] = ci;
    }

    // weights + masked prob-dots over exact top-10
    float radius = sqrtf(fmaxf(rd[0], 0.f));
    const float* prow = (i < NS) ? zip + (size_t)i * CC : zjp + (size_t)(i - NS) * CC;
    float4 myp = ((const float4*)prow)[lane];
    const int im = i & (NS - 1);
    const int li = label[im];
    float rowsum = 0.f;
    #pragma unroll
    for (int r = 0; r < 10; r++) {
        int j = rc[r];
        int jm = j & (NS - 1);
        if (li == label[jm] && li != -1 && im != jm) {
            const float* pr = (j < NS) ? zip + (size_t)j * CC : zjp + (size_t)(j - NS) * CC;
            float4 q4 = ((const float4*)pr)[lane];
            float part = myp.x * q4.x + myp.y * q4.y + myp.z * q4.z + myp.w * q4.w;
            #pragma unroll
            for (int o = 16; o; o >>= 1) part += __shfl_xor_sync(0xffffffffu, part, o);
            float pd = sqrtf(fmaxf(rd[r], 0.f));
            float ww = 1.f - fminf(fmaxf((pd - radius) / radius, 0.f), 1.f);
            rowsum += ww * part;
        }
    }
    if (lane == 0) g_part[i] = rowsum;

    // ---- last-block deterministic reduction ----
    __shared__ int s_last;
    __shared__ float s_red[256];
    __threadfence();
    __syncthreads();
    if (threadIdx.x == 0) s_last = (atomicAdd(&g_ctr, 1) == gridDim.x - 1) ? 1 : 0;
    __syncthreads();
    if (s_last) {
        int tdx = threadIdx.x;
        float a = 0.f;
        #pragma unroll
        for (int q = 0; q < 16; q++) a += g_part[tdx + 256 * q];
        s_red[tdx] = a;
        __syncthreads();
        for (int o = 128; o; o >>= 1) {
            if (tdx < o) s_red[tdx] += s_red[tdx + o];
            __syncthreads();
        }
        if (tdx == 0) out[0] = s_red[0] * (1.0f / ((float)BB * (float)BB));
    }
}

// ---------------------------------------------------------------------------
extern "C" void kernel_launch(void* const* d_in, const int* in_sizes, int n_in,
                              void* d_out, int out_size) {
    const float* z_i = (const float*)d_in[0];
    const float* z_j = (const float*)d_in[1];
    const float* z_i_prob = (const float*)d_in[2];
    const float* z_j_prob = (const float*)d_in[3];
    const int* pseudo_label = (const int*)d_in[4];
    float* out = (float*)d_out;

    cudaFuncSetAttribute(gemm_select_kernel,
                         cudaFuncAttributeMaxDynamicSharedMemorySize, DYN_SMEM);

    convsq_kernel<<<BB / 8, 256>>>(z_i, z_j);
    gemm_select_kernel<<<NTILES, 256, DYN_SMEM>>>();
    merge_loss_kernel<<<BB / 8, 256>>>(z_i, z_j, z_i_prob, z_j_prob, pseudo_label, out);
}